// round 4
// baseline (speedup 1.0000x reference)
#include <cuda_runtime.h>

// ---------------------------------------------------------------------------
// AdaptiveSystem: 2-expert CNN MoE.
// conv1 (3->64, 3x3 s2, 224->112) : fp32 direct conv (FMA pipe)
// conv2 (64->128, 3x3 s2, 112->56): mma.sync tf32 implicit GEMM (A-split
//                                   2xTF32 for fp32-grade weights), fused GAP.
// gate: softmax-max <= 0.9  <=>  |l0-l1| <= ln(9)
// NOTE: toolchain targets sm_103 (no 'a'), so tcgen05 is unavailable;
//       mma.sync is the only tensor-core path that compiles.
// ---------------------------------------------------------------------------

#define NB 64
#define EXP_STRIDE ((size_t)NB * 64 * 112 * 112)

__device__ float g_h1[2 * NB * 64 * 112 * 112];   // ~411 MB scratch (2 experts)
__device__ float g_w2hi[2 * 128 * 576];
__device__ float g_w2lo[2 * 128 * 576];
__device__ float g_gap[2 * NB * 128];             // pooled sums per expert
__device__ float g_tlog[NB * 2];
__device__ int   g_mask[NB];

__device__ __forceinline__ unsigned f2tf(float v) {
    unsigned r;
    asm("cvt.rna.tf32.f32 %0, %1;" : "=r"(r) : "f"(v));
    return r;
}

__device__ __forceinline__ void mma_tf32(float* c, const unsigned* a,
                                         const unsigned* b) {
    asm volatile(
        "mma.sync.aligned.m16n8k8.row.col.f32.tf32.tf32.f32 "
        "{%0,%1,%2,%3}, {%4,%5,%6,%7}, {%8,%9}, {%0,%1,%2,%3};"
        : "+f"(c[0]), "+f"(c[1]), "+f"(c[2]), "+f"(c[3])
        : "r"(a[0]), "r"(a[1]), "r"(a[2]), "r"(a[3]),
          "r"(b[0]), "r"(b[1]));
}

// ---------------------------------------------------------------------------

__global__ void zero_gap_kernel() {
    int i = blockIdx.x * blockDim.x + threadIdx.x;
    if (i < 2 * NB * 128) g_gap[i] = 0.f;
}

__global__ void prep_w2_kernel(const float* __restrict__ t_w2,
                               const float* __restrict__ f_w2)
{
    int i = blockIdx.x * 256 + threadIdx.x;
    if (i >= 128 * 576) return;
    float vt = t_w2[i];
    unsigned h = f2tf(vt);
    g_w2hi[i] = __uint_as_float(h);
    g_w2lo[i] = __uint_as_float(f2tf(vt - __uint_as_float(h)));
    float vf = f_w2[i];
    unsigned hf = f2tf(vf);
    g_w2hi[128 * 576 + i] = __uint_as_float(hf);
    g_w2lo[128 * 576 + i] = __uint_as_float(f2tf(vf - __uint_as_float(hf)));
}

// ---------------------------------------------------------------------------
// conv1: 3 -> 64, 3x3, stride 2, SAME (pad_lo=0, pad_hi=1), 224 -> 112, +ReLU
// grid: (49 tiles, 64 images, 2 experts), block 256. Output tile 16x16.
// ---------------------------------------------------------------------------
__global__ void __launch_bounds__(256) conv1_kernel(
    const float* __restrict__ x,
    const float* __restrict__ t_w1, const float* __restrict__ t_b1,
    const float* __restrict__ f_w1, const float* __restrict__ f_b1)
{
    __shared__ float sIn[3 * 33 * 33];
    __shared__ __align__(16) float sW[64 * 28];
    __shared__ float sB[64];

    int expert = blockIdx.z;
    const float* w    = expert ? f_w1 : t_w1;
    const float* bias = expert ? f_b1 : t_b1;

    int b = blockIdx.y;
    int tile = blockIdx.x;
    int ty = tile / 7, tx = tile % 7;
    int tid = threadIdx.x;
    int y0 = ty * 32, x0 = tx * 32;

    for (int i = tid; i < 3 * 33 * 33; i += 256) {
        int c = i / 1089, rem = i % 1089;
        int iy = rem / 33, ix = rem % 33;
        int gy = y0 + iy, gx = x0 + ix;
        float v = 0.f;
        if (gy < 224 && gx < 224)
            v = x[((b * 3 + c) * 224 + gy) * 224 + gx];
        sIn[i] = v;
    }
    for (int i = tid; i < 64 * 27; i += 256) {
        int oc = i / 27, k = i % 27;
        sW[oc * 28 + k] = w[i];
    }
    if (tid < 64) sB[tid] = bias[tid];
    __syncthreads();

    int ly = tid / 16, lx = tid % 16;
    float rin[27];
    #pragma unroll
    for (int c = 0; c < 3; c++)
        #pragma unroll
        for (int r = 0; r < 3; r++)
            #pragma unroll
            for (int s = 0; s < 3; s++)
                rin[c * 9 + r * 3 + s] = sIn[c * 1089 + (2 * ly + r) * 33 + (2 * lx + s)];

    int oy = ty * 16 + ly, ox = tx * 16 + lx;
    float* outp = &g_h1[expert * EXP_STRIDE + (size_t)b * 64 * 112 * 112 + oy * 112 + ox];

    for (int oc = 0; oc < 64; oc++) {
        float4 wv4[7];
        const float4* wp4 = (const float4*)(sW + oc * 28);
        #pragma unroll
        for (int t = 0; t < 7; t++) wv4[t] = wp4[t];
        const float* wv = (const float*)wv4;
        float acc = sB[oc];
        #pragma unroll
        for (int k = 0; k < 27; k++) acc = fmaf(rin[k], wv[k], acc);
        outp[oc * (112 * 112)] = fmaxf(acc, 0.f);
    }
}

// ---------------------------------------------------------------------------
// conv2 via mma.sync tf32:  D[128 oc][32 px] per block, K = 576 (18 x 32).
// 8 warps = 4(M) x 2(N); warp tile 32 oc x 16 px (2 m16-tiles x 2 n8-tiles).
// A = weights (hi+lo tf32 from global prep), B = im2col gather of h1 (tf32).
// Epilogue: bias + ReLU + quad-shuffle row sums -> atomicAdd into GAP.
// grid: (98 px-blocks, 64 images, 2 experts), block 256.
// ---------------------------------------------------------------------------
#define ASTR 36   // 32 + 4 pad: (36*g + t) % 32 distinct -> conflict-free

__global__ void __launch_bounds__(256) conv2_mma_kernel(
    const float* __restrict__ t_b2, const float* __restrict__ f_b2)
{
    __shared__ float sAh[128 * ASTR];
    __shared__ float sAl[128 * ASTR];
    __shared__ float sB[32 * ASTR];

    int tid = threadIdx.x;
    int wid = tid >> 5, lane = tid & 31;
    int g = lane >> 2, tig = lane & 3;

    int expert = blockIdx.z;
    int img = blockIdx.y;
    int p0 = blockIdx.x * 32;

    const float* h1  = g_h1 + expert * EXP_STRIDE + (size_t)img * (64 * 112 * 112);
    const float* wHi = g_w2hi + expert * (128 * 576);
    const float* wLo = g_w2lo + expert * (128 * 576);
    const float* bs  = expert ? f_b2 : t_b2;

    int warpM = wid >> 1, warpN = wid & 1;
    int ocw = warpM * 32, pxw = warpN * 16;

    float acc[2][2][4];
    #pragma unroll
    for (int mt = 0; mt < 2; mt++)
        #pragma unroll
        for (int nt = 0; nt < 2; nt++)
            #pragma unroll
            for (int i = 0; i < 4; i++) acc[mt][nt][i] = 0.f;

    for (int kb = 0; kb < 576; kb += 32) {
        __syncthreads();
        // ---- stage A: 128 oc x 32 k (hi + lo), coalesced from global ----
        #pragma unroll
        for (int i = tid; i < 4096; i += 256) {
            int oc = i >> 5, kk = i & 31;
            sAh[oc * ASTR + kk] = wHi[oc * 576 + kb + kk];
            sAl[oc * ASTR + kk] = wLo[oc * 576 + kb + kk];
        }
        // ---- stage B: im2col gather, 32 k x 32 px, cvt to tf32 ----
        #pragma unroll
        for (int i = tid; i < 1024; i += 256) {
            int kk = i >> 5, px = i & 31;
            int k = kb + kk;
            int p = p0 + px, y = p / 56, xx = p - y * 56;
            int ch = k / 9, t9 = k - ch * 9, r = t9 / 3, s = t9 - r * 3;
            int row = 2 * y + r, col = 2 * xx + s;
            float v = 0.f;
            if (row < 112 && col < 112)
                v = h1[ch * 12544 + row * 112 + col];
            sB[kk * ASTR + px] = __uint_as_float(f2tf(v));
        }
        __syncthreads();

        // ---- 4 k-steps of m16n8k8 ----
        #pragma unroll
        for (int ks = 0; ks < 4; ks++) {
            int kk0 = ks * 8;
            unsigned bf[2][2];
            #pragma unroll
            for (int nt = 0; nt < 2; nt++) {
                int cidx = pxw + nt * 8 + g;
                bf[nt][0] = __float_as_uint(sB[(kk0 + tig) * ASTR + cidx]);
                bf[nt][1] = __float_as_uint(sB[(kk0 + tig + 4) * ASTR + cidx]);
            }
            #pragma unroll
            for (int mt = 0; mt < 2; mt++) {
                int rb = (ocw + mt * 16 + g) * ASTR + kk0 + tig;
                unsigned ah[4], al[4];
                ah[0] = __float_as_uint(sAh[rb]);
                ah[1] = __float_as_uint(sAh[rb + 8 * ASTR]);
                ah[2] = __float_as_uint(sAh[rb + 4]);
                ah[3] = __float_as_uint(sAh[rb + 8 * ASTR + 4]);
                al[0] = __float_as_uint(sAl[rb]);
                al[1] = __float_as_uint(sAl[rb + 8 * ASTR]);
                al[2] = __float_as_uint(sAl[rb + 4]);
                al[3] = __float_as_uint(sAl[rb + 8 * ASTR + 4]);
                #pragma unroll
                for (int nt = 0; nt < 2; nt++) {
                    mma_tf32(acc[mt][nt], ah, bf[nt]);
                    mma_tf32(acc[mt][nt], al, bf[nt]);
                }
            }
        }
    }

    // ---- epilogue: bias + ReLU + GAP partial sums ----
    float* gap = &g_gap[expert * (NB * 128) + img * 128];
    #pragma unroll
    for (int mt = 0; mt < 2; mt++) {
        int oc0 = ocw + mt * 16 + g;      // rows oc0, oc0+8
        float bv0 = __ldg(&bs[oc0]);
        float bv1 = __ldg(&bs[oc0 + 8]);
        float s0 = 0.f, s1 = 0.f;
        #pragma unroll
        for (int nt = 0; nt < 2; nt++) {
            s0 += fmaxf(acc[mt][nt][0] + bv0, 0.f) + fmaxf(acc[mt][nt][1] + bv0, 0.f);
            s1 += fmaxf(acc[mt][nt][2] + bv1, 0.f) + fmaxf(acc[mt][nt][3] + bv1, 0.f);
        }
        // reduce across the 4 lanes of each quad (same g, tig = 0..3)
        s0 += __shfl_xor_sync(0xffffffffu, s0, 1);
        s0 += __shfl_xor_sync(0xffffffffu, s0, 2);
        s1 += __shfl_xor_sync(0xffffffffu, s1, 1);
        s1 += __shfl_xor_sync(0xffffffffu, s1, 2);
        if (tig == 0) {
            atomicAdd(&gap[oc0], s0);
            atomicAdd(&gap[oc0 + 8], s1);
        }
    }
}

// ---------------------------------------------------------------------------
// texture-expert logits + gate mask.  conf<=0.9  <=>  |l0-l1| <= ln(9)
// ---------------------------------------------------------------------------
__global__ void logits_t_kernel(const float* __restrict__ wf,
                                const float* __restrict__ bf)
{
    int b = threadIdx.x;
    if (b >= NB) return;
    float l0 = bf[0], l1 = bf[1];
    const float inv = 1.0f / 3136.0f;
    for (int k = 0; k < 128; k++) {
        float g = g_gap[b * 128 + k] * inv;
        l0 = fmaf(g, wf[2 * k], l0);
        l1 = fmaf(g, wf[2 * k + 1], l1);
    }
    g_tlog[2 * b] = l0;
    g_tlog[2 * b + 1] = l1;
    g_mask[b] = (fabsf(l0 - l1) <= 2.1972245773362196f) ? 1 : 0;
}

__global__ void final_kernel(const float* __restrict__ wf,
                             const float* __restrict__ bf,
                             float* __restrict__ out)
{
    __shared__ int cnt[NB];
    int b = threadIdx.x;
    if (b < NB) {
        float l0 = bf[0], l1 = bf[1];
        const float inv = 1.0f / 3136.0f;
        for (int k = 0; k < 128; k++) {
            float g = g_gap[NB * 128 + b * 128 + k] * inv;
            l0 = fmaf(g, wf[2 * k], l0);
            l1 = fmaf(g, wf[2 * k + 1], l1);
        }
        int m = g_mask[b];
        float t0 = g_tlog[2 * b], t1 = g_tlog[2 * b + 1];
        out[2 * b]     = m ? (0.7f * t0 + 0.3f * l0) : t0;
        out[2 * b + 1] = m ? (0.7f * t1 + 0.3f * l1) : t1;
        cnt[b] = m;
    }
    __syncthreads();
    if (b == 0) {
        int c = 0;
        for (int i = 0; i < NB; i++) c += cnt[i];
        out[128] = (float)c / (float)NB;
    }
}

extern "C" void kernel_launch(void* const* d_in, const int* in_sizes, int n_in,
                              void* d_out, int out_size)
{
    const float* x    = (const float*)d_in[0];
    const float* t_w1 = (const float*)d_in[1];
    const float* t_b1 = (const float*)d_in[2];
    const float* t_w2 = (const float*)d_in[3];
    const float* t_b2 = (const float*)d_in[4];
    const float* t_wf = (const float*)d_in[5];
    const float* t_bf = (const float*)d_in[6];
    const float* f_w1 = (const float*)d_in[7];
    const float* f_b1 = (const float*)d_in[8];
    const float* f_w2 = (const float*)d_in[9];
    const float* f_b2 = (const float*)d_in[10];
    const float* f_wf = (const float*)d_in[11];
    const float* f_bf = (const float*)d_in[12];
    float* out = (float*)d_out;

    zero_gap_kernel<<<32, 512>>>();
    prep_w2_kernel<<<(128 * 576 + 255) / 256, 256>>>(t_w2, f_w2);
    conv1_kernel<<<dim3(49, 64, 2), 256>>>(x, t_w1, t_b1, f_w1, f_b1);
    conv2_mma_kernel<<<dim3(98, 64, 2), 256>>>(t_b2, f_b2);
    logits_t_kernel<<<1, 64>>>(t_wf, t_bf);
    final_kernel<<<1, 64>>>(f_wf, f_bf, out);
}

// round 5
// speedup vs baseline: 2.9928x; 2.9928x over previous
#include <cuda_runtime.h>

// ---------------------------------------------------------------------------
// AdaptiveSystem: 2-expert CNN MoE.
// conv1 (3->64, 3x3 s2, 224->112) : fp32 direct conv (FMA pipe)
// conv2 (64->128, 3x3 s2, 112->56): mma.sync tf32 implicit GEMM, weights
//     pre-permuted into fragment order (hi+lo 2xTF32 A-split), fused GAP.
// gate: softmax-max <= 0.9  <=>  |l0-l1| <= ln(9)
// ---------------------------------------------------------------------------

#define NB 64
#define EXP_STRIDE ((size_t)NB * 64 * 112 * 112)

// fragment-ordered weights: [expert][chunk(18)][ks(4)][tile(8)][lane(32)][8]
//   per lane: {a_hi[4], a_lo[4]}  (32 bytes, 2x float4)
#define WFRAG_PER_EXPERT (18 * 4 * 8 * 32 * 8)

__device__ float g_h1[2 * NB * 64 * 112 * 112];   // ~411 MB scratch (2 experts)
__device__ __align__(16) float g_w2f[2 * WFRAG_PER_EXPERT];
__device__ float g_gap[2 * NB * 128];
__device__ float g_tlog[NB * 2];
__device__ int   g_mask[NB];

__device__ __forceinline__ unsigned f2tf(float v) {
    unsigned r;
    asm("cvt.rna.tf32.f32 %0, %1;" : "=r"(r) : "f"(v));
    return r;
}

__device__ __forceinline__ void mma_tf32(float* c, const unsigned* a,
                                         const unsigned* b) {
    asm volatile(
        "mma.sync.aligned.m16n8k8.row.col.f32.tf32.tf32.f32 "
        "{%0,%1,%2,%3}, {%4,%5,%6,%7}, {%8,%9}, {%0,%1,%2,%3};"
        : "+f"(c[0]), "+f"(c[1]), "+f"(c[2]), "+f"(c[3])
        : "r"(a[0]), "r"(a[1]), "r"(a[2]), "r"(a[3]),
          "r"(b[0]), "r"(b[1]));
}

// ---------------------------------------------------------------------------

__global__ void zero_gap_kernel() {
    int i = blockIdx.x * blockDim.x + threadIdx.x;
    if (i < 2 * NB * 128) g_gap[i] = 0.f;
}

// Pre-permute conv2 weights into mma-fragment order, hi/lo tf32 split.
// One thread per (expert, chunk, ks, tile, lane): writes 8 floats.
__global__ void prep_w2_kernel(const float* __restrict__ t_w2,
                               const float* __restrict__ f_w2)
{
    int idx = blockIdx.x * 256 + threadIdx.x;
    if (idx >= 2 * 18 * 4 * 8 * 32) return;
    int lane = idx & 31;
    int t = idx >> 5;
    int tile = t & 7;  t >>= 3;
    int ks = t & 3;    t >>= 2;
    int q = t % 18;
    int expert = t / 18;

    const float* w = expert ? f_w2 : t_w2;   // [128][576], k = c*9+r*3+s
    int g = lane >> 2, tig = lane & 3;
    int oc0 = tile * 16 + g;
    int k0 = q * 32 + ks * 8 + tig;

    float v00 = w[oc0 * 576 + k0];            // A[g][tig]
    float v10 = w[(oc0 + 8) * 576 + k0];      // A[g+8][tig]
    float v01 = w[oc0 * 576 + k0 + 4];        // A[g][tig+4]
    float v11 = w[(oc0 + 8) * 576 + k0 + 4];  // A[g+8][tig+4]

    unsigned h0 = f2tf(v00), h1 = f2tf(v10), h2 = f2tf(v01), h3 = f2tf(v11);
    float4 hv = make_float4(__uint_as_float(h0), __uint_as_float(h1),
                            __uint_as_float(h2), __uint_as_float(h3));
    float4 lv = make_float4(
        __uint_as_float(f2tf(v00 - __uint_as_float(h0))),
        __uint_as_float(f2tf(v10 - __uint_as_float(h1))),
        __uint_as_float(f2tf(v01 - __uint_as_float(h2))),
        __uint_as_float(f2tf(v11 - __uint_as_float(h3))));

    float4* dst = (float4*)&g_w2f[(size_t)expert * WFRAG_PER_EXPERT + (size_t)idx % (18*4*8*32) * 8];
    // NOTE: idx % per-expert-count == (((q*4+ks)*8+tile)*32+lane)
    dst[0] = hv;
    dst[1] = lv;
}

// ---------------------------------------------------------------------------
// conv1: 3 -> 64, 3x3, stride 2, SAME (pad_lo=0, pad_hi=1), 224 -> 112, +ReLU
// grid: (49 tiles, 64 images, 2 experts), block 256. Output tile 16x16.
// ---------------------------------------------------------------------------
__global__ void __launch_bounds__(256) conv1_kernel(
    const float* __restrict__ x,
    const float* __restrict__ t_w1, const float* __restrict__ t_b1,
    const float* __restrict__ f_w1, const float* __restrict__ f_b1)
{
    __shared__ float sIn[3 * 33 * 33];
    __shared__ __align__(16) float sW[64 * 28];
    __shared__ float sB[64];

    int expert = blockIdx.z;
    const float* w    = expert ? f_w1 : t_w1;
    const float* bias = expert ? f_b1 : t_b1;

    int b = blockIdx.y;
    int tile = blockIdx.x;
    int ty = tile / 7, tx = tile % 7;
    int tid = threadIdx.x;
    int y0 = ty * 32, x0 = tx * 32;

    for (int i = tid; i < 3 * 33 * 33; i += 256) {
        int c = i / 1089, rem = i % 1089;
        int iy = rem / 33, ix = rem % 33;
        int gy = y0 + iy, gx = x0 + ix;
        float v = 0.f;
        if (gy < 224 && gx < 224)
            v = x[((b * 3 + c) * 224 + gy) * 224 + gx];
        sIn[i] = v;
    }
    for (int i = tid; i < 64 * 27; i += 256) {
        int oc = i / 27, k = i % 27;
        sW[oc * 28 + k] = w[i];
    }
    if (tid < 64) sB[tid] = bias[tid];
    __syncthreads();

    int ly = tid / 16, lx = tid % 16;
    float rin[27];
    #pragma unroll
    for (int c = 0; c < 3; c++)
        #pragma unroll
        for (int r = 0; r < 3; r++)
            #pragma unroll
            for (int s = 0; s < 3; s++)
                rin[c * 9 + r * 3 + s] = sIn[c * 1089 + (2 * ly + r) * 33 + (2 * lx + s)];

    int oy = ty * 16 + ly, ox = tx * 16 + lx;
    float* outp = &g_h1[expert * EXP_STRIDE + (size_t)b * 64 * 112 * 112 + oy * 112 + ox];

    for (int oc = 0; oc < 64; oc++) {
        float4 wv4[7];
        const float4* wp4 = (const float4*)(sW + oc * 28);
        #pragma unroll
        for (int t = 0; t < 7; t++) wv4[t] = wp4[t];
        const float* wv = (const float*)wv4;
        float acc = sB[oc];
        #pragma unroll
        for (int k = 0; k < 27; k++) acc = fmaf(rin[k], wv[k], acc);
        outp[oc * (112 * 112)] = fmaxf(acc, 0.f);
    }
}

// ---------------------------------------------------------------------------
// conv2 via mma.sync tf32:  D[128 oc][64 px] per block, K = 576 (18 x 32).
// 8 warps = 4(M) x 2(N); warp tile = 32 oc x 32 px (2 m16 x 4 n8 tiles).
// A fragments: direct LDG.128 from fragment-ordered global (L1-resident).
// B: im2col gather -> smem (stride 72, conflict-free), tf32.
// Epilogue: bias + ReLU + quad-shuffle row sums -> atomicAdd into GAP.
// grid: (49 px-blocks, 64 images, 2 experts), block 256.
// ---------------------------------------------------------------------------
#define BSTR 72   // 64 + 8 pad: (72*tig + g) % 32 = (8*tig + g) distinct

__global__ void __launch_bounds__(256) conv2_mma_kernel(
    const float* __restrict__ t_b2, const float* __restrict__ f_b2)
{
    __shared__ float sB[32 * BSTR];

    int tid = threadIdx.x;
    int wid = tid >> 5, lane = tid & 31;
    int g = lane >> 2, tig = lane & 3;

    int expert = blockIdx.z;
    int img = blockIdx.y;
    int p0 = blockIdx.x * 64;

    const float* h1 = g_h1 + expert * EXP_STRIDE + (size_t)img * (64 * 112 * 112);
    const float* wf = g_w2f + (size_t)expert * WFRAG_PER_EXPERT;
    const float* bs = expert ? f_b2 : t_b2;

    int warpM = wid >> 1, warpN = wid & 1;
    int ocw = warpM * 32, pxw = warpN * 32;

    float acc[2][4][4];
    #pragma unroll
    for (int mt = 0; mt < 2; mt++)
        #pragma unroll
        for (int nt = 0; nt < 4; nt++)
            #pragma unroll
            for (int i = 0; i < 4; i++) acc[mt][nt][i] = 0.f;

    // this thread's px for the gather is fixed: px = tid & 63
    int px = tid & 63;
    int p = p0 + px, y = p / 56, xx = p - y * 56;
    int brow0 = 2 * y, bcol0 = 2 * xx;

    for (int q = 0; q < 18; q++) {
        __syncthreads();
        // ---- stage B: im2col gather, 32 k x 64 px ----
        int kb = q * 32;
        #pragma unroll
        for (int j = 0; j < 8; j++) {
            int kk = (tid >> 6) + j * 4;
            int k = kb + kk;
            int ch = k / 9, t9 = k - ch * 9, r = t9 / 3, s = t9 - r * 3;
            int row = brow0 + r, col = bcol0 + s;
            float v = 0.f;
            if (row < 112 && col < 112)
                v = h1[ch * 12544 + row * 112 + col];
            sB[kk * BSTR + px] = __uint_as_float(f2tf(v));
        }
        __syncthreads();

        // ---- 4 k-steps of m16n8k8, A frags straight from global ----
        #pragma unroll
        for (int ks = 0; ks < 4; ks++) {
            unsigned bf[4][2];
            #pragma unroll
            for (int nt = 0; nt < 4; nt++) {
                int cidx = pxw + nt * 8 + g;
                bf[nt][0] = __float_as_uint(sB[(ks * 8 + tig) * BSTR + cidx]);
                bf[nt][1] = __float_as_uint(sB[(ks * 8 + tig + 4) * BSTR + cidx]);
            }
            #pragma unroll
            for (int mt = 0; mt < 2; mt++) {
                const float4* ap = (const float4*)&wf[
                    ((((q * 4 + ks) * 8) + warpM * 2 + mt) * 32 + lane) * 8];
                float4 hv = __ldg(&ap[0]);
                float4 lv = __ldg(&ap[1]);
                unsigned ah[4] = {__float_as_uint(hv.x), __float_as_uint(hv.y),
                                  __float_as_uint(hv.z), __float_as_uint(hv.w)};
                unsigned al[4] = {__float_as_uint(lv.x), __float_as_uint(lv.y),
                                  __float_as_uint(lv.z), __float_as_uint(lv.w)};
                #pragma unroll
                for (int nt = 0; nt < 4; nt++) {
                    mma_tf32(acc[mt][nt], ah, bf[nt]);
                    mma_tf32(acc[mt][nt], al, bf[nt]);
                }
            }
        }
    }

    // ---- epilogue: bias + ReLU + GAP partial sums ----
    float* gap = &g_gap[expert * (NB * 128) + img * 128];
    #pragma unroll
    for (int mt = 0; mt < 2; mt++) {
        int oc0 = ocw + mt * 16 + g;      // rows oc0, oc0+8
        float bv0 = __ldg(&bs[oc0]);
        float bv1 = __ldg(&bs[oc0 + 8]);
        float s0 = 0.f, s1 = 0.f;
        #pragma unroll
        for (int nt = 0; nt < 4; nt++) {
            s0 += fmaxf(acc[mt][nt][0] + bv0, 0.f) + fmaxf(acc[mt][nt][1] + bv0, 0.f);
            s1 += fmaxf(acc[mt][nt][2] + bv1, 0.f) + fmaxf(acc[mt][nt][3] + bv1, 0.f);
        }
        s0 += __shfl_xor_sync(0xffffffffu, s0, 1);
        s0 += __shfl_xor_sync(0xffffffffu, s0, 2);
        s1 += __shfl_xor_sync(0xffffffffu, s1, 1);
        s1 += __shfl_xor_sync(0xffffffffu, s1, 2);
        if (tig == 0) {
            atomicAdd(&gap[oc0], s0);
            atomicAdd(&gap[oc0 + 8], s1);
        }
    }
}

// ---------------------------------------------------------------------------
// texture-expert logits + gate mask.  conf<=0.9  <=>  |l0-l1| <= ln(9)
// ---------------------------------------------------------------------------
__global__ void logits_t_kernel(const float* __restrict__ wf,
                                const float* __restrict__ bf)
{
    int b = threadIdx.x;
    if (b >= NB) return;
    float l0 = bf[0], l1 = bf[1];
    const float inv = 1.0f / 3136.0f;
    for (int k = 0; k < 128; k++) {
        float g = g_gap[b * 128 + k] * inv;
        l0 = fmaf(g, wf[2 * k], l0);
        l1 = fmaf(g, wf[2 * k + 1], l1);
    }
    g_tlog[2 * b] = l0;
    g_tlog[2 * b + 1] = l1;
    g_mask[b] = (fabsf(l0 - l1) <= 2.1972245773362196f) ? 1 : 0;
}

__global__ void final_kernel(const float* __restrict__ wf,
                             const float* __restrict__ bf,
                             float* __restrict__ out)
{
    __shared__ int cnt[NB];
    int b = threadIdx.x;
    if (b < NB) {
        float l0 = bf[0], l1 = bf[1];
        const float inv = 1.0f / 3136.0f;
        for (int k = 0; k < 128; k++) {
            float g = g_gap[NB * 128 + b * 128 + k] * inv;
            l0 = fmaf(g, wf[2 * k], l0);
            l1 = fmaf(g, wf[2 * k + 1], l1);
        }
        int m = g_mask[b];
        float t0 = g_tlog[2 * b], t1 = g_tlog[2 * b + 1];
        out[2 * b]     = m ? (0.7f * t0 + 0.3f * l0) : t0;
        out[2 * b + 1] = m ? (0.7f * t1 + 0.3f * l1) : t1;
        cnt[b] = m;
    }
    __syncthreads();
    if (b == 0) {
        int c = 0;
        for (int i = 0; i < NB; i++) c += cnt[i];
        out[128] = (float)c / (float)NB;
    }
}

extern "C" void kernel_launch(void* const* d_in, const int* in_sizes, int n_in,
                              void* d_out, int out_size)
{
    const float* x    = (const float*)d_in[0];
    const float* t_w1 = (const float*)d_in[1];
    const float* t_b1 = (const float*)d_in[2];
    const float* t_w2 = (const float*)d_in[3];
    const float* t_b2 = (const float*)d_in[4];
    const float* t_wf = (const float*)d_in[5];
    const float* t_bf = (const float*)d_in[6];
    const float* f_w1 = (const float*)d_in[7];
    const float* f_b1 = (const float*)d_in[8];
    const float* f_w2 = (const float*)d_in[9];
    const float* f_b2 = (const float*)d_in[10];
    const float* f_wf = (const float*)d_in[11];
    const float* f_bf = (const float*)d_in[12];
    float* out = (float*)d_out;

    zero_gap_kernel<<<32, 512>>>();
    prep_w2_kernel<<<(2 * 18 * 4 * 8 * 32 + 255) / 256, 256>>>(t_w2, f_w2);
    conv1_kernel<<<dim3(49, 64, 2), 256>>>(x, t_w1, t_b1, f_w1, f_b1);
    conv2_mma_kernel<<<dim3(49, 64, 2), 256>>>(t_b2, f_b2);
    logits_t_kernel<<<1, 64>>>(t_wf, t_bf);
    final_kernel<<<1, 64>>>(f_wf, f_bf, out);
}

// round 6
// speedup vs baseline: 3.1287x; 1.0454x over previous
#include <cuda_runtime.h>

// ---------------------------------------------------------------------------
// AdaptiveSystem: 2-expert CNN MoE.
// conv1 (3->64, 3x3 s2, 224->112) : fp32 direct conv; writes h1 in
//     parity-split layout [ch][row][col&1][col>>1] for contiguous im2col.
// conv2 (64->128, 3x3 s2, 112->56): mma.sync tf32 implicit GEMM, weights
//     pre-permuted to fragment order (hi+lo 2xTF32 A-split), warp = 32oc x
//     56px (one output row), double-buffered B smem, fused GAP.
// gate: softmax-max <= 0.9  <=>  |l0-l1| <= ln(9)
// ---------------------------------------------------------------------------

#define NB 64
#define EXP_STRIDE ((size_t)NB * 64 * 112 * 112)

// fragment-ordered weights: [expert][chunk(18)][ks(4)][tile(8)][lane(32)][8]
#define WFRAG_PER_EXPERT (18 * 4 * 8 * 32 * 8)

__device__ float g_h1[2 * NB * 64 * 112 * 112];   // parity-split, ~411 MB
__device__ __align__(16) float g_w2f[2 * WFRAG_PER_EXPERT];
__device__ float g_gap[2 * NB * 128];
__device__ float g_tlog[NB * 2];
__device__ int   g_mask[NB];

__device__ __forceinline__ unsigned f2tf(float v) {
    unsigned r;
    asm("cvt.rna.tf32.f32 %0, %1;" : "=r"(r) : "f"(v));
    return r;
}

__device__ __forceinline__ void mma_tf32(float* c, const unsigned* a,
                                         const unsigned* b) {
    asm volatile(
        "mma.sync.aligned.m16n8k8.row.col.f32.tf32.tf32.f32 "
        "{%0,%1,%2,%3}, {%4,%5,%6,%7}, {%8,%9}, {%0,%1,%2,%3};"
        : "+f"(c[0]), "+f"(c[1]), "+f"(c[2]), "+f"(c[3])
        : "r"(a[0]), "r"(a[1]), "r"(a[2]), "r"(a[3]),
          "r"(b[0]), "r"(b[1]));
}

// ---------------------------------------------------------------------------

__global__ void zero_gap_kernel() {
    int i = blockIdx.x * blockDim.x + threadIdx.x;
    if (i < 2 * NB * 128) g_gap[i] = 0.f;
}

// Pre-permute conv2 weights into mma-fragment order, hi/lo tf32 split.
__global__ void prep_w2_kernel(const float* __restrict__ t_w2,
                               const float* __restrict__ f_w2)
{
    int idx = blockIdx.x * 256 + threadIdx.x;
    if (idx >= 2 * 18 * 4 * 8 * 32) return;
    int lane = idx & 31;
    int t = idx >> 5;
    int tile = t & 7;  t >>= 3;
    int ks = t & 3;    t >>= 2;
    int q = t % 18;
    int expert = t / 18;

    const float* w = expert ? f_w2 : t_w2;   // [128][576], k = c*9+r*3+s
    int g = lane >> 2, tig = lane & 3;
    int oc0 = tile * 16 + g;
    int k0 = q * 32 + ks * 8 + tig;

    float v00 = w[oc0 * 576 + k0];
    float v10 = w[(oc0 + 8) * 576 + k0];
    float v01 = w[oc0 * 576 + k0 + 4];
    float v11 = w[(oc0 + 8) * 576 + k0 + 4];

    unsigned h0 = f2tf(v00), h1 = f2tf(v10), h2 = f2tf(v01), h3 = f2tf(v11);
    float4 hv = make_float4(__uint_as_float(h0), __uint_as_float(h1),
                            __uint_as_float(h2), __uint_as_float(h3));
    float4 lv = make_float4(
        __uint_as_float(f2tf(v00 - __uint_as_float(h0))),
        __uint_as_float(f2tf(v10 - __uint_as_float(h1))),
        __uint_as_float(f2tf(v01 - __uint_as_float(h2))),
        __uint_as_float(f2tf(v11 - __uint_as_float(h3))));

    float4* dst = (float4*)&g_w2f[(size_t)expert * WFRAG_PER_EXPERT
                                  + (size_t)(idx % (18 * 4 * 8 * 32)) * 8];
    dst[0] = hv;
    dst[1] = lv;
}

// ---------------------------------------------------------------------------
// conv1: 3 -> 64, 3x3, stride 2, SAME, 224 -> 112, +ReLU.
// Output stored parity-split: h1[ch][row][ox&1][ox>>1].
// grid: (49 tiles, 64 images, 2 experts), block 256. Output tile 16x16.
// ---------------------------------------------------------------------------
__global__ void __launch_bounds__(256) conv1_kernel(
    const float* __restrict__ x,
    const float* __restrict__ t_w1, const float* __restrict__ t_b1,
    const float* __restrict__ f_w1, const float* __restrict__ f_b1)
{
    __shared__ float sIn[3 * 33 * 33];
    __shared__ __align__(16) float sW[64 * 28];
    __shared__ float sB[64];

    int expert = blockIdx.z;
    const float* w    = expert ? f_w1 : t_w1;
    const float* bias = expert ? f_b1 : t_b1;

    int b = blockIdx.y;
    int tile = blockIdx.x;
    int ty = tile / 7, tx = tile % 7;
    int tid = threadIdx.x;
    int y0 = ty * 32, x0 = tx * 32;

    for (int i = tid; i < 3 * 33 * 33; i += 256) {
        int c = i / 1089, rem = i % 1089;
        int iy = rem / 33, ix = rem % 33;
        int gy = y0 + iy, gx = x0 + ix;
        float v = 0.f;
        if (gy < 224 && gx < 224)
            v = x[((b * 3 + c) * 224 + gy) * 224 + gx];
        sIn[i] = v;
    }
    for (int i = tid; i < 64 * 27; i += 256) {
        int oc = i / 27, k = i % 27;
        sW[oc * 28 + k] = w[i];
    }
    if (tid < 64) sB[tid] = bias[tid];
    __syncthreads();

    int ly = tid / 16, lx = tid % 16;
    float rin[27];
    #pragma unroll
    for (int c = 0; c < 3; c++)
        #pragma unroll
        for (int r = 0; r < 3; r++)
            #pragma unroll
            for (int s = 0; s < 3; s++)
                rin[c * 9 + r * 3 + s] = sIn[c * 1089 + (2 * ly + r) * 33 + (2 * lx + s)];

    int oy = ty * 16 + ly, ox = tx * 16 + lx;
    // parity-split store address
    float* outp = &g_h1[expert * EXP_STRIDE + (size_t)b * 64 * 112 * 112
                        + oy * 112 + (ox & 1) * 56 + (ox >> 1)];

    for (int oc = 0; oc < 64; oc++) {
        float4 wv4[7];
        const float4* wp4 = (const float4*)(sW + oc * 28);
        #pragma unroll
        for (int t = 0; t < 7; t++) wv4[t] = wp4[t];
        const float* wv = (const float*)wv4;
        float acc = sB[oc];
        #pragma unroll
        for (int k = 0; k < 27; k++) acc = fmaf(rin[k], wv[k], acc);
        outp[oc * (112 * 112)] = fmaxf(acc, 0.f);
    }
}

// ---------------------------------------------------------------------------
// conv2 via mma.sync tf32:  D[128 oc][56 px] per block (one output row y).
// 4 warps, all M: warp = 32 oc (2 m16) x 56 px (7 n8).  K = 576 (18 x 32).
// A frags: LDG.128 from fragment-ordered global. B: contiguous gather from
// parity-split h1 -> double-buffered pair-major float2 smem (conflict-free).
// Epilogue: bias + ReLU + quad-shuffle row sums -> atomicAdd into GAP.
// grid: (56 rows, 64 images, 2 experts), block 128.
// ---------------------------------------------------------------------------
#define PADP 68   // float2 units per pair-row: (4*tig + g) mod 16 bijective

__global__ void __launch_bounds__(128) conv2_mma_kernel(
    const float* __restrict__ t_b2, const float* __restrict__ f_b2)
{
    __shared__ float2 sB[2][16 * PADP];

    int tid = threadIdx.x;
    int wid = tid >> 5, lane = tid & 31;
    int g = lane >> 2, tig = lane & 3;

    int expert = blockIdx.z;
    int img = blockIdx.y;
    int y = blockIdx.x;          // output row 0..55

    const float* h1 = g_h1 + expert * EXP_STRIDE + (size_t)img * (64 * 112 * 112);
    const float* wf = g_w2f + (size_t)expert * WFRAG_PER_EXPERT;
    const float* bs = expert ? f_b2 : t_b2;

    float acc[2][7][4];
    #pragma unroll
    for (int mt = 0; mt < 2; mt++)
        #pragma unroll
        for (int nt = 0; nt < 7; nt++)
            #pragma unroll
            for (int i = 0; i < 4; i++) acc[mt][nt][i] = 0.f;

    // gather staging registers: 7 iterations x (k0,k1) pair, 896 = 7*128 exact
    float v0[7], v1[7];

    // ---- load phase for chunk q into (v0,v1) ----
    auto load_chunk = [&](int q) {
        int kb = q * 32;
        #pragma unroll
        for (int j = 0; j < 7; j++) {
            int i = j * 128 + tid;
            int pair = i / 56, px = i - pair * 56;
            int kqs = pair >> 2, ktg = pair & 3;
            int k0 = kb + kqs * 8 + ktg;
            int k1 = k0 + 4;
            // k0
            {
                int ch = k0 / 9, t9 = k0 - ch * 9, r = t9 / 3, s = t9 - r * 3;
                int row = 2 * y + r;
                int idx = px + (s >> 1);
                float v = 0.f;
                if (row < 112 && idx < 56)
                    v = h1[ch * 12544 + row * 112 + (s & 1) * 56 + idx];
                v0[j] = v;
            }
            // k1
            {
                int ch = k1 / 9, t9 = k1 - ch * 9, r = t9 / 3, s = t9 - r * 3;
                int row = 2 * y + r;
                int idx = px + (s >> 1);
                float v = 0.f;
                if (row < 112 && idx < 56)
                    v = h1[ch * 12544 + row * 112 + (s & 1) * 56 + idx];
                v1[j] = v;
            }
        }
    };

    load_chunk(0);

    for (int q = 0; q < 18; q++) {
        int buf = q & 1;
        // ---- store phase: regs -> smem (tf32 round) ----
        #pragma unroll
        for (int j = 0; j < 7; j++) {
            int i = j * 128 + tid;
            int pair = i / 56, px = i - pair * 56;
            sB[buf][pair * PADP + px] =
                make_float2(__uint_as_float(f2tf(v0[j])),
                            __uint_as_float(f2tf(v1[j])));
        }
        __syncthreads();
        if (q < 17) load_chunk(q + 1);

        // ---- MMA phase on buf ----
        #pragma unroll
        for (int ks = 0; ks < 4; ks++) {
            float2 bp[7];
            #pragma unroll
            for (int nt = 0; nt < 7; nt++)
                bp[nt] = sB[buf][(ks * 4 + tig) * PADP + nt * 8 + g];
            #pragma unroll
            for (int mt = 0; mt < 2; mt++) {
                const float4* ap = (const float4*)&wf[
                    ((((q * 4 + ks) * 8) + wid * 2 + mt) * 32 + lane) * 8];
                float4 hv = __ldg(&ap[0]);
                float4 lv = __ldg(&ap[1]);
                unsigned ah[4] = {__float_as_uint(hv.x), __float_as_uint(hv.y),
                                  __float_as_uint(hv.z), __float_as_uint(hv.w)};
                unsigned al[4] = {__float_as_uint(lv.x), __float_as_uint(lv.y),
                                  __float_as_uint(lv.z), __float_as_uint(lv.w)};
                #pragma unroll
                for (int nt = 0; nt < 7; nt++) {
                    unsigned bfr[2] = {__float_as_uint(bp[nt].x),
                                       __float_as_uint(bp[nt].y)};
                    mma_tf32(acc[mt][nt], ah, bfr);
                    mma_tf32(acc[mt][nt], al, bfr);
                }
            }
        }
        __syncthreads();
    }

    // ---- epilogue: bias + ReLU + GAP partial sums ----
    float* gap = &g_gap[expert * (NB * 128) + img * 128];
    #pragma unroll
    for (int mt = 0; mt < 2; mt++) {
        int oc0 = wid * 32 + mt * 16 + g;
        float bv0 = __ldg(&bs[oc0]);
        float bv1 = __ldg(&bs[oc0 + 8]);
        float s0 = 0.f, s1 = 0.f;
        #pragma unroll
        for (int nt = 0; nt < 7; nt++) {
            s0 += fmaxf(acc[mt][nt][0] + bv0, 0.f) + fmaxf(acc[mt][nt][1] + bv0, 0.f);
            s1 += fmaxf(acc[mt][nt][2] + bv1, 0.f) + fmaxf(acc[mt][nt][3] + bv1, 0.f);
        }
        s0 += __shfl_xor_sync(0xffffffffu, s0, 1);
        s0 += __shfl_xor_sync(0xffffffffu, s0, 2);
        s1 += __shfl_xor_sync(0xffffffffu, s1, 1);
        s1 += __shfl_xor_sync(0xffffffffu, s1, 2);
        if (tig == 0) {
            atomicAdd(&gap[oc0], s0);
            atomicAdd(&gap[oc0 + 8], s1);
        }
    }
}

// ---------------------------------------------------------------------------
// texture-expert logits + gate mask.  conf<=0.9  <=>  |l0-l1| <= ln(9)
// ---------------------------------------------------------------------------
__global__ void logits_t_kernel(const float* __restrict__ wf,
                                const float* __restrict__ bf)
{
    int b = threadIdx.x;
    if (b >= NB) return;
    float l0 = bf[0], l1 = bf[1];
    const float inv = 1.0f / 3136.0f;
    for (int k = 0; k < 128; k++) {
        float g = g_gap[b * 128 + k] * inv;
        l0 = fmaf(g, wf[2 * k], l0);
        l1 = fmaf(g, wf[2 * k + 1], l1);
    }
    g_tlog[2 * b] = l0;
    g_tlog[2 * b + 1] = l1;
    g_mask[b] = (fabsf(l0 - l1) <= 2.1972245773362196f) ? 1 : 0;
}

__global__ void final_kernel(const float* __restrict__ wf,
                             const float* __restrict__ bf,
                             float* __restrict__ out)
{
    __shared__ int cnt[NB];
    int b = threadIdx.x;
    if (b < NB) {
        float l0 = bf[0], l1 = bf[1];
        const float inv = 1.0f / 3136.0f;
        for (int k = 0; k < 128; k++) {
            float g = g_gap[NB * 128 + b * 128 + k] * inv;
            l0 = fmaf(g, wf[2 * k], l0);
            l1 = fmaf(g, wf[2 * k + 1], l1);
        }
        int m = g_mask[b];
        float t0 = g_tlog[2 * b], t1 = g_tlog[2 * b + 1];
        out[2 * b]     = m ? (0.7f * t0 + 0.3f * l0) : t0;
        out[2 * b + 1] = m ? (0.7f * t1 + 0.3f * l1) : t1;
        cnt[b] = m;
    }
    __syncthreads();
    if (b == 0) {
        int c = 0;
        for (int i = 0; i < NB; i++) c += cnt[i];
        out[128] = (float)c / (float)NB;
    }
}

extern "C" void kernel_launch(void* const* d_in, const int* in_sizes, int n_in,
                              void* d_out, int out_size)
{
    const float* x    = (const float*)d_in[0];
    const float* t_w1 = (const float*)d_in[1];
    const float* t_b1 = (const float*)d_in[2];
    const float* t_w2 = (const float*)d_in[3];
    const float* t_b2 = (const float*)d_in[4];
    const float* t_wf = (const float*)d_in[5];
    const float* t_bf = (const float*)d_in[6];
    const float* f_w1 = (const float*)d_in[7];
    const float* f_b1 = (const float*)d_in[8];
    const float* f_w2 = (const float*)d_in[9];
    const float* f_b2 = (const float*)d_in[10];
    const float* f_wf = (const float*)d_in[11];
    const float* f_bf = (const float*)d_in[12];
    float* out = (float*)d_out;

    zero_gap_kernel<<<32, 512>>>();
    prep_w2_kernel<<<(2 * 18 * 4 * 8 * 32 + 255) / 256, 256>>>(t_w2, f_w2);
    conv1_kernel<<<dim3(49, 64, 2), 256>>>(x, t_w1, t_b1, f_w1, f_b1);
    conv2_mma_kernel<<<dim3(56, 64, 2), 128>>>(t_b2, f_b2);
    logits_t_kernel<<<1, 64>>>(t_wf, t_bf);
    final_kernel<<<1, 64>>>(f_wf, f_bf, out);
}

// round 7
// speedup vs baseline: 4.3474x; 1.3895x over previous
#include <cuda_runtime.h>

// ---------------------------------------------------------------------------
// AdaptiveSystem: 2-expert CNN MoE.
// conv1 (3->64, 3x3 s2, 224->112) : fp32 direct conv; h1 stored parity-split
//     [ch][row][col&1][col>>1] so conv2's stride-2 im2col is contiguous.
// conv2 (64->128, 3x3 s2, 112->56): mma.sync tf32 implicit GEMM, single-pass
//     RNA tf32 (logit err ~1e-4, gate-safe), fragment-ordered weights,
//     table-driven gather, double-buffered B smem, fused GAP.
// gate: softmax-max <= 0.9  <=>  |l0-l1| <= ln(9)
// ---------------------------------------------------------------------------

#define NB 64
#define EXP_STRIDE ((size_t)NB * 64 * 112 * 112)

// fragment-ordered weights: [expert][chunk(18)][ks(4)][tile(8)][lane(32)][4]
#define WFRAG_PER_EXPERT (18 * 4 * 8 * 32 * 4)

__device__ float g_h1[2 * NB * 64 * 112 * 112];   // parity-split, ~411 MB
__device__ __align__(16) float g_w2f[2 * WFRAG_PER_EXPERT];
__device__ unsigned g_imoff[576];                 // off | (r==2)<<24 | (s==2)<<25
__device__ float g_gap[2 * NB * 128];

__device__ __forceinline__ unsigned f2tf(float v) {
    unsigned r;
    asm("cvt.rna.tf32.f32 %0, %1;" : "=r"(r) : "f"(v));
    return r;
}

__device__ __forceinline__ void mma_tf32(float* c, const unsigned* a,
                                         const unsigned* b) {
    asm volatile(
        "mma.sync.aligned.m16n8k8.row.col.f32.tf32.tf32.f32 "
        "{%0,%1,%2,%3}, {%4,%5,%6,%7}, {%8,%9}, {%0,%1,%2,%3};"
        : "+f"(c[0]), "+f"(c[1]), "+f"(c[2]), "+f"(c[3])
        : "r"(a[0]), "r"(a[1]), "r"(a[2]), "r"(a[3]),
          "r"(b[0]), "r"(b[1]));
}

// ---------------------------------------------------------------------------

__global__ void zero_gap_kernel() {
    int i = blockIdx.x * blockDim.x + threadIdx.x;
    if (i < 2 * NB * 128) g_gap[i] = 0.f;
    if (i < 576) {
        int ch = i / 9, t9 = i % 9, r = t9 / 3, s = t9 % 3;
        unsigned off = ch * 12544 + r * 112 + (s & 1) * 56 + (s >> 1);
        g_imoff[i] = off | ((r == 2) ? (1u << 24) : 0) | ((s == 2) ? (1u << 25) : 0);
    }
}

// Pre-permute conv2 weights into mma-fragment order (single RNA tf32).
__global__ void prep_w2_kernel(const float* __restrict__ t_w2,
                               const float* __restrict__ f_w2)
{
    int idx = blockIdx.x * 256 + threadIdx.x;
    if (idx >= 2 * 18 * 4 * 8 * 32) return;
    int lane = idx & 31;
    int t = idx >> 5;
    int tile = t & 7;  t >>= 3;
    int ks = t & 3;    t >>= 2;
    int q = t % 18;
    int expert = t / 18;

    const float* w = expert ? f_w2 : t_w2;   // [128][576], k = c*9+r*3+s
    int g = lane >> 2, tig = lane & 3;
    int oc0 = tile * 16 + g;
    int k0 = q * 32 + ks * 8 + tig;

    float4 hv = make_float4(
        __uint_as_float(f2tf(w[oc0 * 576 + k0])),
        __uint_as_float(f2tf(w[(oc0 + 8) * 576 + k0])),
        __uint_as_float(f2tf(w[oc0 * 576 + k0 + 4])),
        __uint_as_float(f2tf(w[(oc0 + 8) * 576 + k0 + 4])));

    *(float4*)&g_w2f[(size_t)expert * WFRAG_PER_EXPERT
                     + (size_t)(idx % (18 * 4 * 8 * 32)) * 4] = hv;
}

// ---------------------------------------------------------------------------
// conv1: 3 -> 64, 3x3, stride 2, SAME, 224 -> 112, +ReLU, parity-split store.
// grid: (49 tiles, 64 images, 2 experts), block 256. Output tile 16x16.
// ---------------------------------------------------------------------------
__global__ void __launch_bounds__(256) conv1_kernel(
    const float* __restrict__ x,
    const float* __restrict__ t_w1, const float* __restrict__ t_b1,
    const float* __restrict__ f_w1, const float* __restrict__ f_b1)
{
    __shared__ float sIn[3 * 33 * 33];
    __shared__ __align__(16) float sW[64 * 28];
    __shared__ float sB[64];

    int expert = blockIdx.z;
    const float* w    = expert ? f_w1 : t_w1;
    const float* bias = expert ? f_b1 : t_b1;

    int b = blockIdx.y;
    int tile = blockIdx.x;
    int ty = tile / 7, tx = tile % 7;
    int tid = threadIdx.x;
    int y0 = ty * 32, x0 = tx * 32;

    for (int i = tid; i < 3 * 33 * 33; i += 256) {
        int c = i / 1089, rem = i % 1089;
        int iy = rem / 33, ix = rem % 33;
        int gy = y0 + iy, gx = x0 + ix;
        float v = 0.f;
        if (gy < 224 && gx < 224)
            v = x[((b * 3 + c) * 224 + gy) * 224 + gx];
        sIn[i] = v;
    }
    for (int i = tid; i < 64 * 27; i += 256) {
        int oc = i / 27, k = i % 27;
        sW[oc * 28 + k] = w[i];
    }
    if (tid < 64) sB[tid] = bias[tid];
    __syncthreads();

    int ly = tid / 16, lx = tid % 16;
    float rin[27];
    #pragma unroll
    for (int c = 0; c < 3; c++)
        #pragma unroll
        for (int r = 0; r < 3; r++)
            #pragma unroll
            for (int s = 0; s < 3; s++)
                rin[c * 9 + r * 3 + s] = sIn[c * 1089 + (2 * ly + r) * 33 + (2 * lx + s)];

    int oy = ty * 16 + ly, ox = tx * 16 + lx;
    float* outp = &g_h1[expert * EXP_STRIDE + (size_t)b * 64 * 112 * 112
                        + oy * 112 + (ox & 1) * 56 + (ox >> 1)];

    for (int oc = 0; oc < 64; oc++) {
        float4 wv4[7];
        const float4* wp4 = (const float4*)(sW + oc * 28);
        #pragma unroll
        for (int t = 0; t < 7; t++) wv4[t] = wp4[t];
        const float* wv = (const float*)wv4;
        float acc = sB[oc];
        #pragma unroll
        for (int k = 0; k < 27; k++) acc = fmaf(rin[k], wv[k], acc);
        outp[oc * (112 * 112)] = fmaxf(acc, 0.f);
    }
}

// ---------------------------------------------------------------------------
// conv2 via mma.sync tf32:  D[128 oc][56 px] per block (one output row y).
// 4 warps, all M: warp = 32 oc (2 m16) x 56 px (7 n8).  K = 576 (18 x 32).
// A frags: 1 LDG.128 each from fragment-ordered global (L1-resident).
// B: table-driven contiguous gather from parity-split h1 -> double-buffered
//    pair-major float2 smem (conflict-free).  Fused GAP epilogue.
// grid: (56 rows, 64 images, 2 experts), block 128.
// ---------------------------------------------------------------------------
#define PADP 68

__global__ void __launch_bounds__(128, 4) conv2_mma_kernel(
    const float* __restrict__ t_b2, const float* __restrict__ f_b2)
{
    __shared__ float2 sB[2][16 * PADP];

    int tid = threadIdx.x;
    int wid = tid >> 5, lane = tid & 31;
    int g = lane >> 2, tig = lane & 3;

    int expert = blockIdx.z;
    int img = blockIdx.y;
    int y = blockIdx.x;          // output row 0..55

    const float* h1 = g_h1 + expert * EXP_STRIDE + (size_t)img * (64 * 112 * 112)
                    + y * 224;                     // + row offset (2y*112)
    const float* wfrag = g_w2f + (size_t)expert * WFRAG_PER_EXPERT
                       + (size_t)(wid * 2) * 32 * 4 + lane * 4;
    const float* bs = expert ? f_b2 : t_b2;

    bool y55 = (y == 55);

    float acc[2][7][4];
    #pragma unroll
    for (int mt = 0; mt < 2; mt++)
        #pragma unroll
        for (int nt = 0; nt < 7; nt++)
            #pragma unroll
            for (int i = 0; i < 4; i++) acc[mt][nt][i] = 0.f;

    // per-j gather geometry (constant across chunks)
    int koff[7], smix[7], pxj[7];
    bool px55[7];
    #pragma unroll
    for (int j = 0; j < 7; j++) {
        int i = j * 128 + tid;
        int pair = i / 56, px = i - pair * 56;
        int kqs = pair >> 2, ktg = pair & 3;
        koff[j] = kqs * 8 + ktg;
        smix[j] = pair * PADP + px;
        pxj[j] = px;
        px55[j] = (px == 55);
    }

    float v0[7], v1[7];
    auto load_chunk = [&](int kb) {
        #pragma unroll
        for (int j = 0; j < 7; j++) {
            unsigned e0 = __ldg(&g_imoff[kb + koff[j]]);
            unsigned e1 = __ldg(&g_imoff[kb + koff[j] + 4]);
            float a = 0.f, b = 0.f;
            if (!(((e0 >> 24) & 1) & y55) && !(((e0 >> 25) & 1) & px55[j]))
                a = h1[(e0 & 0xFFFFFF) + pxj[j]];
            if (!(((e1 >> 24) & 1) & y55) && !(((e1 >> 25) & 1) & px55[j]))
                b = h1[(e1 & 0xFFFFFF) + pxj[j]];
            v0[j] = a; v1[j] = b;
        }
    };

    load_chunk(0);

    for (int q = 0; q < 18; q++) {
        int buf = q & 1;
        #pragma unroll
        for (int j = 0; j < 7; j++)
            sB[buf][smix[j]] = make_float2(__uint_as_float(f2tf(v0[j])),
                                           __uint_as_float(f2tf(v1[j])));
        __syncthreads();
        if (q < 17) load_chunk((q + 1) * 32);

        const float* ap = wfrag + (size_t)q * 4096;   // chunk stride 4*8*32*4
        #pragma unroll
        for (int ks = 0; ks < 4; ks++) {
            float2 bp[7];
            #pragma unroll
            for (int nt = 0; nt < 7; nt++)
                bp[nt] = sB[buf][(ks * 4 + tig) * PADP + nt * 8 + g];
            #pragma unroll
            for (int mt = 0; mt < 2; mt++) {
                float4 hv = __ldg((const float4*)(ap + (ks * 8 + mt) * 128));
                unsigned ah[4] = {__float_as_uint(hv.x), __float_as_uint(hv.y),
                                  __float_as_uint(hv.z), __float_as_uint(hv.w)};
                #pragma unroll
                for (int nt = 0; nt < 7; nt++) {
                    unsigned bfr[2] = {__float_as_uint(bp[nt].x),
                                       __float_as_uint(bp[nt].y)};
                    mma_tf32(acc[mt][nt], ah, bfr);
                }
            }
        }
        __syncthreads();
    }

    // ---- epilogue: bias + ReLU + GAP partial sums ----
    float* gap = &g_gap[expert * (NB * 128) + img * 128];
    #pragma unroll
    for (int mt = 0; mt < 2; mt++) {
        int oc0 = wid * 32 + mt * 16 + g;
        float bv0 = __ldg(&bs[oc0]);
        float bv1 = __ldg(&bs[oc0 + 8]);
        float s0 = 0.f, s1 = 0.f;
        #pragma unroll
        for (int nt = 0; nt < 7; nt++) {
            s0 += fmaxf(acc[mt][nt][0] + bv0, 0.f) + fmaxf(acc[mt][nt][1] + bv0, 0.f);
            s1 += fmaxf(acc[mt][nt][2] + bv1, 0.f) + fmaxf(acc[mt][nt][3] + bv1, 0.f);
        }
        s0 += __shfl_xor_sync(0xffffffffu, s0, 1);
        s0 += __shfl_xor_sync(0xffffffffu, s0, 2);
        s1 += __shfl_xor_sync(0xffffffffu, s1, 1);
        s1 += __shfl_xor_sync(0xffffffffu, s1, 2);
        if (tig == 0) {
            atomicAdd(&gap[oc0], s0);
            atomicAdd(&gap[oc0 + 8], s1);
        }
    }
}

// ---------------------------------------------------------------------------
// final: both experts' logits, gate, blend, freq.  1 block x 64 threads.
// ---------------------------------------------------------------------------
__global__ void final_kernel(const float* __restrict__ t_wf,
                             const float* __restrict__ t_bf,
                             const float* __restrict__ f_wf,
                             const float* __restrict__ f_bf,
                             float* __restrict__ out)
{
    __shared__ int cnt[NB];
    int b = threadIdx.x;
    if (b < NB) {
        float tl0 = t_bf[0], tl1 = t_bf[1];
        float fl0 = f_bf[0], fl1 = f_bf[1];
        const float inv = 1.0f / 3136.0f;
        for (int k = 0; k < 128; k++) {
            float gt = g_gap[b * 128 + k] * inv;
            float gf = g_gap[NB * 128 + b * 128 + k] * inv;
            tl0 = fmaf(gt, t_wf[2 * k], tl0);
            tl1 = fmaf(gt, t_wf[2 * k + 1], tl1);
            fl0 = fmaf(gf, f_wf[2 * k], fl0);
            fl1 = fmaf(gf, f_wf[2 * k + 1], fl1);
        }
        int m = (fabsf(tl0 - tl1) <= 2.1972245773362196f) ? 1 : 0;
        out[2 * b]     = m ? (0.7f * tl0 + 0.3f * fl0) : tl0;
        out[2 * b + 1] = m ? (0.7f * tl1 + 0.3f * fl1) : tl1;
        cnt[b] = m;
    }
    __syncthreads();
    if (b == 0) {
        int c = 0;
        for (int i = 0; i < NB; i++) c += cnt[i];
        out[128] = (float)c / (float)NB;
    }
}

extern "C" void kernel_launch(void* const* d_in, const int* in_sizes, int n_in,
                              void* d_out, int out_size)
{
    const float* x    = (const float*)d_in[0];
    const float* t_w1 = (const float*)d_in[1];
    const float* t_b1 = (const float*)d_in[2];
    const float* t_w2 = (const float*)d_in[3];
    const float* t_b2 = (const float*)d_in[4];
    const float* t_wf = (const float*)d_in[5];
    const float* t_bf = (const float*)d_in[6];
    const float* f_w1 = (const float*)d_in[7];
    const float* f_b1 = (const float*)d_in[8];
    const float* f_w2 = (const float*)d_in[9];
    const float* f_b2 = (const float*)d_in[10];
    const float* f_wf = (const float*)d_in[11];
    const float* f_bf = (const float*)d_in[12];
    float* out = (float*)d_out;

    zero_gap_kernel<<<32, 512>>>();
    prep_w2_kernel<<<(2 * 18 * 4 * 8 * 32 + 255) / 256, 256>>>(t_w2, f_w2);
    conv1_kernel<<<dim3(49, 64, 2), 256>>>(x, t_w1, t_b1, f_w1, f_b1);
    conv2_mma_kernel<<<dim3(56, 64, 2), 128>>>(t_b2, f_b2);
    final_kernel<<<1, 64>>>(t_wf, t_bf, f_wf, f_bf, out);
}